// round 15
// baseline (speedup 1.0000x reference)
#include <cuda_runtime.h>
#include <cuda_fp16.h>
#include <cstdint>
#include <math.h>

// Problem constants
#define BB 4
#define TT 2048
#define CC 512
#define HH 8
#define HD 64
#define MM (BB*TT)          // 8192
#define BH (BB*HH)          // 32

// ---------------- device scratch (fp16) ----------------
__device__ __half g_xh[MM * CC];
__device__ __half g_wqkvh[3 * CC * CC];
__device__ __half g_wouth[CC * CC];
__device__ __half g_qh[BH * TT * HD];
__device__ __half g_kh[BH * TT * HD];
__device__ __half g_vh[BH * TT * HD];
__device__ __half g_atth[MM * CC];

// ---------------- helpers ----------------
__device__ __forceinline__ unsigned pack_h2(float x, float y) {
    __half2 h = __floats2half2_rn(x, y);
    return *(unsigned*)&h;
}

__device__ __forceinline__ void mma_f16(float& c0, float& c1, float& c2, float& c3,
                                        unsigned a0, unsigned a1, unsigned a2, unsigned a3,
                                        unsigned b0, unsigned b1) {
    asm volatile(
        "mma.sync.aligned.m16n8k16.row.col.f32.f16.f16.f32 "
        "{%0,%1,%2,%3}, {%4,%5,%6,%7}, {%8,%9}, {%0,%1,%2,%3};"
        : "+f"(c0), "+f"(c1), "+f"(c2), "+f"(c3)
        : "r"(a0), "r"(a1), "r"(a2), "r"(a3), "r"(b0), "r"(b1));
}

__device__ __forceinline__ void ldsm_x4(unsigned& r0, unsigned& r1, unsigned& r2, unsigned& r3,
                                        uint32_t addr) {
    asm volatile("ldmatrix.sync.aligned.m8n8.x4.shared.b16 {%0,%1,%2,%3}, [%4];"
                 : "=r"(r0), "=r"(r1), "=r"(r2), "=r"(r3) : "r"(addr));
}

__device__ __forceinline__ void ldsm_x4_t(unsigned& r0, unsigned& r1, unsigned& r2, unsigned& r3,
                                          uint32_t addr) {
    asm volatile("ldmatrix.sync.aligned.m8n8.x4.trans.shared.b16 {%0,%1,%2,%3}, [%4];"
                 : "=r"(r0), "=r"(r1), "=r"(r2), "=r"(r3) : "r"(addr));
}

__device__ __forceinline__ unsigned ex2_h2(unsigned x) {
    unsigned r;
    asm("ex2.approx.f16x2 %0, %1;" : "=r"(r) : "r"(x));
    return r;
}

#define CP_ASYNC16(dst, src) \
    asm volatile("cp.async.cg.shared.global [%0], [%1], 16;" :: "r"(dst), "l"(src))
#define CP_COMMIT() asm volatile("cp.async.commit_group;" ::: "memory")
#define CP_WAIT0()  asm volatile("cp.async.wait_group 0;" ::: "memory")

// swizzled byte offset: pair-packed rows (two rows per 128B), chunk c in 0..3
__device__ __forceinline__ uint32_t swz(int row, int c) {
    return (uint32_t)(((row >> 1) * 128) +
                      (((((row & 1) << 2) | c) ^ ((row >> 1) & 7)) << 4));
}

// ---------------- fp32 -> fp16 convert (all three tensors, one launch) ----
__global__ void __launch_bounds__(256) f2h3(const float* __restrict__ a, __half* __restrict__ da, int na,
                                            const float* __restrict__ b, __half* __restrict__ db, int nb,
                                            const float* __restrict__ c, __half* __restrict__ dc, int nc) {
    int t = (blockIdx.x * blockDim.x + threadIdx.x) * 4;
    const float* s; __half* d; int i;
    if (t < na)            { s = a; d = da; i = t; }
    else if (t < na + nb)  { s = b; d = db; i = t - na; }
    else if (t < na + nb + nc) { s = c; d = dc; i = t - na - nb; }
    else return;
    float4 v = *(const float4*)(s + i);
    *(uint2*)(d + i) = make_uint2(pack_h2(v.x, v.y), pack_h2(v.z, v.w));
}

// =====================================================================
// GEMM mainloop: fp16 A[M,512] @ W[N,512]^T. Block 128x128, 8 warps
// of 32x64, BK=32, cp.async 2-stage, ldmatrix.x4 with hoisted
// swizzled addresses. 32KB smem, 2 CTAs/SM.
// =====================================================================
#define GEMM_MAINLOOP(Aptr, Wptr)                                              \
    __shared__ __align__(16) char sm[32768];                                   \
    const int tid = threadIdx.x, warp = tid >> 5, lane = tid & 31;             \
    const int g = lane >> 2, q = lane & 3;                                     \
    const int jj = lane >> 3, rr = lane & 7;                                   \
    const int bm = blockIdx.y * 128, bn = blockIdx.x * 128;                    \
    const int wm = (warp >> 1) * 32, wn = (warp & 1) * 64;                     \
    const uint32_t smA0 = (uint32_t)__cvta_generic_to_shared(sm);              \
    const uint32_t smB0 = smA0 + 16384;                                        \
    float acc[2][8][4];                                                        \
    _Pragma("unroll") for (int mi = 0; mi < 2; mi++)                           \
    _Pragma("unroll") for (int ni = 0; ni < 8; ni++)                           \
    _Pragma("unroll") for (int cz = 0; cz < 4; cz++) acc[mi][ni][cz] = 0.f;    \
    uint32_t aAdr[2][2], bAdr[4][2];                                           \
    _Pragma("unroll")                                                          \
    for (int mi = 0; mi < 2; mi++)                                             \
    _Pragma("unroll")                                                          \
    for (int kc = 0; kc < 2; kc++) {                                           \
        int m = wm + mi * 16 + (jj & 1) * 8 + rr;                              \
        aAdr[mi][kc] = smA0 + swz(m, 2 * kc + (jj >> 1));                      \
    }                                                                          \
    _Pragma("unroll")                                                          \
    for (int nb = 0; nb < 4; nb++)                                             \
    _Pragma("unroll")                                                          \
    for (int kc = 0; kc < 2; kc++) {                                           \
        int n = wn + nb * 16 + (jj & 1) * 8 + rr;                              \
        bAdr[nb][kc] = smB0 + swz(n, 2 * kc + (jj >> 1));                      \
    }                                                                          \
    auto load_stage = [&](int s, int koff) {                                   \
        _Pragma("unroll")                                                      \
        for (int i = 0; i < 2; i++) {                                          \
            int idx = tid + i * 256;                                           \
            int m = idx >> 2, cch = idx & 3;                                   \
            CP_ASYNC16(smA0 + s * 8192 + swz(m, cch),                          \
                       (Aptr) + (size_t)(bm + m) * CC + koff + cch * 8);       \
        }                                                                      \
        _Pragma("unroll")                                                      \
        for (int i = 0; i < 2; i++) {                                          \
            int idx = tid + i * 256;                                           \
            int n = idx >> 2, cch = idx & 3;                                   \
            CP_ASYNC16(smB0 + s * 8192 + swz(n, cch),                          \
                       (Wptr) + (size_t)(bn + n) * CC + koff + cch * 8);       \
        }                                                                      \
    };                                                                         \
    load_stage(0, 0);                                                          \
    CP_COMMIT();                                                               \
    CP_WAIT0();                                                                \
    __syncthreads();                                                           \
    int buf = 0;                                                               \
    for (int it = 0; it < 16; it++) {                                          \
        if (it < 15) { load_stage(buf ^ 1, (it + 1) * 32); CP_COMMIT(); }      \
        const uint32_t off = buf * 8192;                                       \
        _Pragma("unroll")                                                      \
        for (int kc = 0; kc < 2; kc++) {                                       \
            unsigned af[2][4];                                                 \
            _Pragma("unroll")                                                  \
            for (int mi = 0; mi < 2; mi++)                                     \
                ldsm_x4(af[mi][0], af[mi][1], af[mi][2], af[mi][3],            \
                        aAdr[mi][kc] + off);                                   \
            unsigned bf[8][2];                                                 \
            _Pragma("unroll")                                                  \
            for (int nb = 0; nb < 4; nb++) {                                   \
                unsigned t0, t1, t2, t3;                                       \
                ldsm_x4(t0, t1, t2, t3, bAdr[nb][kc] + off);                   \
                bf[2 * nb][0] = t0; bf[2 * nb + 1][0] = t1;                    \
                bf[2 * nb][1] = t2; bf[2 * nb + 1][1] = t3;                    \
            }                                                                  \
            _Pragma("unroll")                                                  \
            for (int mi = 0; mi < 2; mi++)                                     \
            _Pragma("unroll")                                                  \
            for (int ni = 0; ni < 8; ni++)                                     \
                mma_f16(acc[mi][ni][0], acc[mi][ni][1],                        \
                        acc[mi][ni][2], acc[mi][ni][3],                        \
                        af[mi][0], af[mi][1], af[mi][2], af[mi][3],            \
                        bf[ni][0], bf[ni][1]);                                 \
        }                                                                      \
        if (it < 15) { CP_WAIT0(); __syncthreads(); buf ^= 1; }                \
    }

// ---- QKV GEMM + fused RoPE + head split (fp16 out) ----
__global__ void __launch_bounds__(256, 2) gemm_qkv_rope_h(
    const __half* __restrict__ A, const __half* __restrict__ W,
    const float* __restrict__ cosp, const float* __restrict__ sinp,
    __half* __restrict__ qo, __half* __restrict__ ko, __half* __restrict__ vo) {
    GEMM_MAINLOOP(A, W)

    const int n0   = bn + wn;          // head-aligned 64-wide warp span
    const int type = n0 >> 9;          // 0=q, 1=k, 2=v
    const int h    = (n0 >> 6) & 7;
    __half* outp = (type == 0) ? qo : (type == 1) ? ko : vo;
    const float sc = (type == 0) ? 0.125f : 1.f;

#pragma unroll
    for (int mi = 0; mi < 2; mi++) {
        const int m  = bm + wm + mi * 16 + g;
        const int b  = m >> 11;
        const int t0 = m & (TT - 1);
        const size_t base0 = ((size_t)(b * HH + h) * TT + t0) * HD;
        const size_t base1 = base0 + 8 * HD;

        if (type == 2) {
#pragma unroll
            for (int ni = 0; ni < 8; ni++) {
                const int d = ni * 8 + 2 * q;
                *(unsigned*)&outp[base0 + d] = pack_h2(acc[mi][ni][0], acc[mi][ni][1]);
                *(unsigned*)&outp[base1 + d] = pack_h2(acc[mi][ni][2], acc[mi][ni][3]);
            }
        } else {
#pragma unroll
            for (int ni = 0; ni < 4; ni++) {
                const int d  = ni * 8 + 2 * q;
                const int du = d + 32;
                float2 cl0 = *(const float2*)&cosp[t0 * HD + d];
                float2 sl0 = *(const float2*)&sinp[t0 * HD + d];
                float2 cu0 = *(const float2*)&cosp[t0 * HD + du];
                float2 su0 = *(const float2*)&sinp[t0 * HD + du];
                float2 cl1 = *(const float2*)&cosp[(t0 + 8) * HD + d];
                float2 sl1 = *(const float2*)&sinp[(t0 + 8) * HD + d];
                float2 cu1 = *(const float2*)&cosp[(t0 + 8) * HD + du];
                float2 su1 = *(const float2*)&sinp[(t0 + 8) * HD + du];

                float x1a = acc[mi][ni][0],     x1b = acc[mi][ni][1];
                float x2a = acc[mi][ni + 4][0], x2b = acc[mi][ni + 4][1];
                *(unsigned*)&outp[base0 + d]  = pack_h2((x1a * cl0.x - x2a * sl0.x) * sc,
                                                        (x1b * cl0.y - x2b * sl0.y) * sc);
                *(unsigned*)&outp[base0 + du] = pack_h2((x2a * cu0.x + x1a * su0.x) * sc,
                                                        (x2b * cu0.y + x1b * su0.y) * sc);
                float y1a = acc[mi][ni][2],     y1b = acc[mi][ni][3];
                float y2a = acc[mi][ni + 4][2], y2b = acc[mi][ni + 4][3];
                *(unsigned*)&outp[base1 + d]  = pack_h2((y1a * cl1.x - y2a * sl1.x) * sc,
                                                        (y1b * cl1.y - y2b * sl1.y) * sc);
                *(unsigned*)&outp[base1 + du] = pack_h2((y2a * cu1.x + y1a * su1.x) * sc,
                                                        (y2b * cu1.y + y1b * su1.y) * sc);
            }
        }
    }
}

// ---- Output projection GEMM (fp16 in, fp32 out) ----
__global__ void __launch_bounds__(256, 2) gemm_out_h(
    const __half* __restrict__ A, const __half* __restrict__ W,
    float* __restrict__ Cmat) {
    GEMM_MAINLOOP(A, W)

#pragma unroll
    for (int mi = 0; mi < 2; mi++) {
#pragma unroll
        for (int ni = 0; ni < 8; ni++) {
            const int m = bm + wm + mi * 16 + g;
            const int n = bn + wn + ni * 8 + 2 * q;
            *(float2*)&Cmat[(size_t)m * CC + n] =
                make_float2(acc[mi][ni][0], acc[mi][ni][1]);
            *(float2*)&Cmat[(size_t)(m + 8) * CC + n] =
                make_float2(acc[mi][ni][2], acc[mi][ni][3]);
        }
    }
}

// =====================================================================
// Flash attention (causal), fp16 in/out, mma m16n8k16.
// q-tile 128 (8 warps), k-tile 64, cp.async double-buffered K/V,
// ldmatrix (K) / ldmatrix.trans (V), f16x2 softmax.
// SINGLE sync per ktile (GEMM-style pipeline: wait after compute),
// and warp-uniform skip of the O rescale when the max is unchanged.
// =====================================================================
__global__ void __launch_bounds__(256) attn_h(const __half* __restrict__ Q,
                                              const __half* __restrict__ K,
                                              const __half* __restrict__ V,
                                              __half* __restrict__ Oatt) {
    __shared__ __align__(16) char sm[32768];   // [stage][K 8KB | V 8KB]
    const uint32_t smb = (uint32_t)__cvta_generic_to_shared(sm);

    const int tid  = threadIdx.x;
    const int warp = tid >> 5;
    const int lane = tid & 31;
    const int g    = lane >> 2;
    const int q    = lane & 3;
    const int lg   = lane >> 3, lr = lane & 7;
    const int qt   = (int)gridDim.x - 1 - (int)blockIdx.x;   // big tiles first
    const int q0   = qt * 128;
    const int bh   = blockIdx.y;
    const int row0 = q0 + warp * 16 + g;
    const int row1 = row0 + 8;
    const float L2E = 1.4426950408889634f;

    uint32_t kAdr[4];
#pragma unroll
    for (int kc = 0; kc < 4; kc++)
        kAdr[kc] = (uint32_t)((8 * (lg >> 1) + lr) * 128 +
                              (((2 * kc + (lg & 1)) ^ lr) << 4));
    uint32_t vAdr[4];
#pragma unroll
    for (int jp = 0; jp < 4; jp++)
        vAdr[jp] = (uint32_t)(8192 + (8 * (lg & 1) + lr) * 128 +
                              (((2 * jp + (lg >> 1)) ^ lr) << 4));

    unsigned Qa[4][4];
    {
        const __half* q0p = Q + ((size_t)bh * TT + row0) * HD;
        const __half* q1p = Q + ((size_t)bh * TT + row1) * HD;
#pragma unroll
        for (int kc = 0; kc < 4; kc++) {
            int d0 = 16 * kc + 2 * q;
            Qa[kc][0] = *(const unsigned*)(q0p + d0);
            Qa[kc][1] = *(const unsigned*)(q1p + d0);
            Qa[kc][2] = *(const unsigned*)(q0p + d0 + 8);
            Qa[kc][3] = *(const unsigned*)(q1p + d0 + 8);
        }
    }

    float Oac[8][4];
#pragma unroll
    for (int j = 0; j < 8; j++)
#pragma unroll
        for (int i = 0; i < 4; i++) Oac[j][i] = 0.f;
    float m0_ = -1e30f, m1_ = -1e30f, l0_ = 0.f, l1_ = 0.f;

    const __half* kbase = K + (size_t)bh * TT * HD;
    const __half* vbase = V + (size_t)bh * TT * HD;

    auto load_tile = [&](int s, int k0) {
#pragma unroll
        for (int i = 0; i < 2; i++) {
            int idx = tid + i * 256;              // 0..511 16B chunks
            int key = idx >> 3, c = idx & 7;
            uint32_t doff = (uint32_t)(key * 128 + (((c ^ (key & 7))) << 4));
            const __half* ks = kbase + (size_t)(k0 + key) * HD + 8 * c;
            const __half* vs = vbase + (size_t)(k0 + key) * HD + 8 * c;
            CP_ASYNC16(smb + s * 16384 + doff, ks);
            CP_ASYNC16(smb + s * 16384 + 8192 + doff, vs);
        }
    };

    const int nkt = 2 * qt + 2;
    load_tile(0, 0);
    CP_COMMIT();
    CP_WAIT0();
    __syncthreads();
    int buf = 0;
    for (int kt = 0; kt < nkt; kt++) {
        const int k0 = kt * 64;
        const bool more = (kt + 1 < nkt);
        if (more) { load_tile(buf ^ 1, k0 + 64); CP_COMMIT(); }
        const uint32_t so = smb + buf * 16384;

        // ---- S = (Q/8) @ K^T ----
        float S[8][4];
#pragma unroll
        for (int j = 0; j < 8; j++)
#pragma unroll
            for (int i = 0; i < 4; i++) S[j][i] = 0.f;

#pragma unroll
        for (int kc = 0; kc < 4; kc++) {
#pragma unroll
            for (int jp = 0; jp < 4; jp++) {
                unsigned b0, b1, b2, b3;
                ldsm_x4(b0, b1, b2, b3, so + kAdr[kc] + jp * 2048);
                mma_f16(S[2 * jp][0], S[2 * jp][1], S[2 * jp][2], S[2 * jp][3],
                        Qa[kc][0], Qa[kc][1], Qa[kc][2], Qa[kc][3], b0, b1);
                mma_f16(S[2 * jp + 1][0], S[2 * jp + 1][1], S[2 * jp + 1][2], S[2 * jp + 1][3],
                        Qa[kc][0], Qa[kc][1], Qa[kc][2], Qa[kc][3], b2, b3);
            }
        }

        // ---- causal mask (last two ktiles straddle the diagonal) ----
        if (kt >= nkt - 2) {
#pragma unroll
            for (int j = 0; j < 8; j++) {
                int c = k0 + 8 * j + 2 * q;
                if (c     > row0) S[j][0] = -1e30f;
                if (c + 1 > row0) S[j][1] = -1e30f;
                if (c     > row1) S[j][2] = -1e30f;
                if (c + 1 > row1) S[j][3] = -1e30f;
            }
        }

        // ---- online softmax (exp via ex2.approx.f16x2) ----
        float tm0 = -1e30f, tm1 = -1e30f;
#pragma unroll
        for (int j = 0; j < 8; j++) {
            tm0 = fmaxf(tm0, fmaxf(S[j][0], S[j][1]));
            tm1 = fmaxf(tm1, fmaxf(S[j][2], S[j][3]));
        }
        tm0 = fmaxf(tm0, __shfl_xor_sync(0xffffffffu, tm0, 1));
        tm0 = fmaxf(tm0, __shfl_xor_sync(0xffffffffu, tm0, 2));
        tm1 = fmaxf(tm1, __shfl_xor_sync(0xffffffffu, tm1, 1));
        tm1 = fmaxf(tm1, __shfl_xor_sync(0xffffffffu, tm1, 2));

        float nm0 = fmaxf(m0_, tm0), nm1 = fmaxf(m1_, tm1);
        float r0 = __expf(m0_ - nm0), r1 = __expf(m1_ - nm1);
        m0_ = nm0; m1_ = nm1;
        const float b0s = nm0 * L2E, b1s = nm1 * L2E;

        unsigned E[8][2];   // E[j][0] = fp16 {p(c0), p(c1)}, E[j][1] = {p(c2), p(c3)}
#pragma unroll
        for (int j = 0; j < 8; j++) {
            float f0 = fmaf(S[j][0], L2E, -b0s);
            float f1 = fmaf(S[j][1], L2E, -b0s);
            float f2 = fmaf(S[j][2], L2E, -b1s);
            float f3 = fmaf(S[j][3], L2E, -b1s);
            E[j][0] = ex2_h2(pack_h2(f0, f1));
            E[j][1] = ex2_h2(pack_h2(f2, f3));
        }

        // row sums via HADD2 tree (sums the exact fp16 P used in PV)
        {
            __half2* Eh = (__half2*)E;
            __half2 s0 = __hadd2(__hadd2(__hadd2(Eh[0],  Eh[2]),  __hadd2(Eh[4],  Eh[6])),
                                 __hadd2(__hadd2(Eh[8],  Eh[10]), __hadd2(Eh[12], Eh[14])));
            __half2 s1 = __hadd2(__hadd2(__hadd2(Eh[1],  Eh[3]),  __hadd2(Eh[5],  Eh[7])),
                                 __hadd2(__hadd2(Eh[9],  Eh[11]), __hadd2(Eh[13], Eh[15])));
            float2 f0 = __half22float2(s0);
            float2 f1 = __half22float2(s1);
            float rs0 = f0.x + f0.y;
            float rs1 = f1.x + f1.y;
            rs0 += __shfl_xor_sync(0xffffffffu, rs0, 1);
            rs0 += __shfl_xor_sync(0xffffffffu, rs0, 2);
            rs1 += __shfl_xor_sync(0xffffffffu, rs1, 1);
            rs1 += __shfl_xor_sync(0xffffffffu, rs1, 2);
            l0_ = l0_ * r0 + rs0;
            l1_ = l1_ * r1 + rs1;
        }

        // rescale O only if some lane's max actually moved (warp-uniform)
        if (__any_sync(0xffffffffu, (r0 != 1.f) | (r1 != 1.f))) {
#pragma unroll
            for (int j = 0; j < 8; j++) {
                Oac[j][0] *= r0; Oac[j][1] *= r0;
                Oac[j][2] *= r1; Oac[j][3] *= r1;
            }
        }

        // ---- O += P @ V (P A-frag = E directly; V via ldmatrix.trans) ----
#pragma unroll
        for (int kc = 0; kc < 4; kc++) {
            unsigned a0 = E[2 * kc][0];
            unsigned a1 = E[2 * kc][1];
            unsigned a2 = E[2 * kc + 1][0];
            unsigned a3 = E[2 * kc + 1][1];
#pragma unroll
            for (int jp = 0; jp < 4; jp++) {
                unsigned b0, b1, b2, b3;
                ldsm_x4_t(b0, b1, b2, b3, so + vAdr[jp] + kc * 2048);
                mma_f16(Oac[2 * jp][0], Oac[2 * jp][1], Oac[2 * jp][2], Oac[2 * jp][3],
                        a0, a1, a2, a3, b0, b1);
                mma_f16(Oac[2 * jp + 1][0], Oac[2 * jp + 1][1], Oac[2 * jp + 1][2], Oac[2 * jp + 1][3],
                        a0, a1, a2, a3, b2, b3);
            }
        }

        if (more) {
            CP_WAIT0();        // next tile landed during compute
            __syncthreads();   // also proves all warps finished reading buf
            buf ^= 1;
        }
    }

    const int b = bh >> 3, h = bh & 7;
    float inv0 = 1.f / l0_, inv1 = 1.f / l1_;
    __half* o0 = Oatt + ((size_t)(b * TT) + row0) * CC + h * HD;
    __half* o1 = Oatt + ((size_t)(b * TT) + row1) * CC + h * HD;
#pragma unroll
    for (int j = 0; j < 8; j++) {
        *(unsigned*)&o0[8 * j + 2 * q] = pack_h2(Oac[j][0] * inv0, Oac[j][1] * inv0);
        *(unsigned*)&o1[8 * j + 2 * q] = pack_h2(Oac[j][2] * inv1, Oac[j][3] * inv1);
    }
}

// =====================================================================
extern "C" void kernel_launch(void* const* d_in, const int* in_sizes, int n_in,
                              void* d_out, int out_size) {
    const float* x    = (const float*)d_in[0];
    const float* cosp = (const float*)d_in[1];
    const float* sinp = (const float*)d_in[2];
    const float* Wqkv = (const float*)d_in[3];
    const float* Wout = (const float*)d_in[4];
    float* out = (float*)d_out;

    __half *xh, *wqkvh, *wouth, *qh, *kh, *vh, *atth;
    cudaGetSymbolAddress((void**)&xh,    g_xh);
    cudaGetSymbolAddress((void**)&wqkvh, g_wqkvh);
    cudaGetSymbolAddress((void**)&wouth, g_wouth);
    cudaGetSymbolAddress((void**)&qh,    g_qh);
    cudaGetSymbolAddress((void**)&kh,    g_kh);
    cudaGetSymbolAddress((void**)&vh,    g_vh);
    cudaGetSymbolAddress((void**)&atth,  g_atth);

    const int na = MM * CC, nb = 3 * CC * CC, nc = CC * CC;
    // 0) fp32 -> fp16 conversion (one launch)
    f2h3<<<(na + nb + nc) / 4 / 256, 256>>>(x, xh, na, Wqkv, wqkvh, nb, Wout, wouth, nc);
    // 1) fused QKV GEMM + RoPE + head-split (fp16 out, q pre-scaled)
    gemm_qkv_rope_h<<<dim3((3 * CC) / 128, MM / 128), 256>>>(
        xh, wqkvh, cosp, sinp, qh, kh, vh);
    // 2) causal flash attention (single-sync pipeline, f16x2 softmax)
    attn_h<<<dim3(TT / 128, BH), 256>>>(qh, kh, vh, atth);
    // 3) out = att @ Wout^T (fp16 in, fp32 out)
    gemm_out_h<<<dim3(CC / 128, MM / 128), 256>>>(atth, wouth, out);
}

// round 16
// speedup vs baseline: 1.1048x; 1.1048x over previous
#include <cuda_runtime.h>
#include <cuda_fp16.h>
#include <cstdint>
#include <math.h>

// Problem constants
#define BB 4
#define TT 2048
#define CC 512
#define HH 8
#define HD 64
#define MM (BB*TT)          // 8192
#define BH (BB*HH)          // 32

// ---------------- device scratch (fp16) ----------------
__device__ __half g_xh[MM * CC];
__device__ __half g_wqkvh[3 * CC * CC];
__device__ __half g_wouth[CC * CC];
__device__ __half g_qh[BH * TT * HD];
__device__ __half g_kh[BH * TT * HD];
__device__ __half g_vh[BH * TT * HD];
__device__ __half g_atth[MM * CC];

// ---------------- helpers ----------------
__device__ __forceinline__ unsigned pack_h2(float x, float y) {
    __half2 h = __floats2half2_rn(x, y);
    return *(unsigned*)&h;
}

__device__ __forceinline__ void mma_f16(float& c0, float& c1, float& c2, float& c3,
                                        unsigned a0, unsigned a1, unsigned a2, unsigned a3,
                                        unsigned b0, unsigned b1) {
    asm volatile(
        "mma.sync.aligned.m16n8k16.row.col.f32.f16.f16.f32 "
        "{%0,%1,%2,%3}, {%4,%5,%6,%7}, {%8,%9}, {%0,%1,%2,%3};"
        : "+f"(c0), "+f"(c1), "+f"(c2), "+f"(c3)
        : "r"(a0), "r"(a1), "r"(a2), "r"(a3), "r"(b0), "r"(b1));
}

__device__ __forceinline__ void ldsm_x4(unsigned& r0, unsigned& r1, unsigned& r2, unsigned& r3,
                                        uint32_t addr) {
    asm volatile("ldmatrix.sync.aligned.m8n8.x4.shared.b16 {%0,%1,%2,%3}, [%4];"
                 : "=r"(r0), "=r"(r1), "=r"(r2), "=r"(r3) : "r"(addr));
}

__device__ __forceinline__ void ldsm_x4_t(unsigned& r0, unsigned& r1, unsigned& r2, unsigned& r3,
                                          uint32_t addr) {
    asm volatile("ldmatrix.sync.aligned.m8n8.x4.trans.shared.b16 {%0,%1,%2,%3}, [%4];"
                 : "=r"(r0), "=r"(r1), "=r"(r2), "=r"(r3) : "r"(addr));
}

__device__ __forceinline__ unsigned ex2_h2(unsigned x) {
    unsigned r;
    asm("ex2.approx.f16x2 %0, %1;" : "=r"(r) : "r"(x));
    return r;
}

#define CP_ASYNC16(dst, src) \
    asm volatile("cp.async.cg.shared.global [%0], [%1], 16;" :: "r"(dst), "l"(src))
#define CP_COMMIT() asm volatile("cp.async.commit_group;" ::: "memory")
#define CP_WAIT0()  asm volatile("cp.async.wait_group 0;" ::: "memory")
#define CP_WAIT1()  asm volatile("cp.async.wait_group 1;" ::: "memory")

// ---------------- fp32 -> fp16 convert (all three tensors, one launch) ----
__global__ void __launch_bounds__(256) f2h3(const float* __restrict__ a, __half* __restrict__ da, int na,
                                            const float* __restrict__ b, __half* __restrict__ db, int nb,
                                            const float* __restrict__ c, __half* __restrict__ dc, int nc) {
    int t = (blockIdx.x * blockDim.x + threadIdx.x) * 4;
    const float* s; __half* d; int i;
    if (t < na)            { s = a; d = da; i = t; }
    else if (t < na + nb)  { s = b; d = db; i = t - na; }
    else if (t < na + nb + nc) { s = c; d = dc; i = t - na - nb; }
    else return;
    float4 v = *(const float4*)(s + i);
    *(uint2*)(d + i) = make_uint2(pack_h2(v.x, v.y), pack_h2(v.z, v.w));
}

// =====================================================================
// GEMM mainloop: fp16 A[M,512] @ W[N,512]^T. Block 128x128, 8 warps
// of 32(m)x64(n), BK=64 (64 HMMA/warp between syncs), cp.async
// 2-stage, 64KB DYNAMIC smem (2 CTAs/SM), 128B-row tiles with
// c^(row&7) chunk swizzle (same layout as the attention tiles).
// =====================================================================
#define GEMM_MAINLOOP(Aptr, Wptr)                                              \
    extern __shared__ __align__(16) char sm[];                                 \
    const int tid = threadIdx.x, warp = tid >> 5, lane = tid & 31;             \
    const int g = lane >> 2, q = lane & 3;                                     \
    const int lg = lane >> 3, lr = lane & 7;                                   \
    const int bm = blockIdx.y * 128, bn = blockIdx.x * 128;                    \
    const int wm = (warp >> 1) * 32, wn = (warp & 1) * 64;                     \
    const uint32_t smA0 = (uint32_t)__cvta_generic_to_shared(sm);              \
    const uint32_t smB0 = smA0 + 32768;                                        \
    float acc[2][8][4];                                                        \
    _Pragma("unroll") for (int mi = 0; mi < 2; mi++)                           \
    _Pragma("unroll") for (int ni = 0; ni < 8; ni++)                           \
    _Pragma("unroll") for (int cz = 0; cz < 4; cz++) acc[mi][ni][cz] = 0.f;    \
    uint32_t rowA[2], rowB[4], coA[4], coB[4];                                 \
    _Pragma("unroll")                                                          \
    for (int mi = 0; mi < 2; mi++)                                             \
        rowA[mi] = smA0 + (uint32_t)((wm + mi * 16 + ((lg & 1) << 3) + lr) * 128); \
    _Pragma("unroll")                                                          \
    for (int nb = 0; nb < 4; nb++)                                             \
        rowB[nb] = smB0 + (uint32_t)((wn + nb * 16 + ((lg >> 1) << 3) + lr) * 128); \
    _Pragma("unroll")                                                          \
    for (int kc = 0; kc < 4; kc++) {                                           \
        coA[kc] = (uint32_t)(((2 * kc + (lg >> 1)) ^ lr) << 4);                \
        coB[kc] = (uint32_t)(((2 * kc + (lg & 1)) ^ lr) << 4);                 \
    }                                                                          \
    auto load_stage = [&](int s, int koff) {                                   \
        _Pragma("unroll")                                                      \
        for (int i = 0; i < 4; i++) {                                          \
            int idx = tid + i * 256;                                           \
            int row = idx >> 3, c = idx & 7;                                   \
            uint32_t doff = (uint32_t)(row * 128 + ((c ^ (row & 7)) << 4));    \
            CP_ASYNC16(smA0 + s * 16384 + doff,                                \
                       (Aptr) + (size_t)(bm + row) * CC + koff + 8 * c);       \
            CP_ASYNC16(smB0 + s * 16384 + doff,                                \
                       (Wptr) + (size_t)(bn + row) * CC + koff + 8 * c);       \
        }                                                                      \
    };                                                                         \
    load_stage(0, 0);                                                          \
    CP_COMMIT();                                                               \
    CP_WAIT0();                                                                \
    __syncthreads();                                                           \
    int buf = 0;                                                               \
    for (int it = 0; it < 8; it++) {                                           \
        if (it < 7) { load_stage(buf ^ 1, (it + 1) * 64); CP_COMMIT(); }       \
        const uint32_t off = buf * 16384;                                      \
        _Pragma("unroll")                                                      \
        for (int kc = 0; kc < 4; kc++) {                                       \
            unsigned af[2][4];                                                 \
            _Pragma("unroll")                                                  \
            for (int mi = 0; mi < 2; mi++)                                     \
                ldsm_x4(af[mi][0], af[mi][1], af[mi][2], af[mi][3],            \
                        rowA[mi] + coA[kc] + off);                             \
            _Pragma("unroll")                                                  \
            for (int nb = 0; nb < 4; nb++) {                                   \
                unsigned b0, b1, b2, b3;                                       \
                ldsm_x4(b0, b1, b2, b3, rowB[nb] + coB[kc] + off);             \
                _Pragma("unroll")                                              \
                for (int mi = 0; mi < 2; mi++) {                               \
                    mma_f16(acc[mi][2 * nb][0], acc[mi][2 * nb][1],            \
                            acc[mi][2 * nb][2], acc[mi][2 * nb][3],            \
                            af[mi][0], af[mi][1], af[mi][2], af[mi][3],        \
                            b0, b1);                                           \
                    mma_f16(acc[mi][2 * nb + 1][0], acc[mi][2 * nb + 1][1],    \
                            acc[mi][2 * nb + 1][2], acc[mi][2 * nb + 1][3],    \
                            af[mi][0], af[mi][1], af[mi][2], af[mi][3],        \
                            b2, b3);                                           \
                }                                                              \
            }                                                                  \
        }                                                                      \
        if (it < 7) { CP_WAIT0(); __syncthreads(); buf ^= 1; }                 \
    }

// ---- QKV GEMM + fused RoPE + head split (fp16 out) ----
__global__ void __launch_bounds__(256, 2) gemm_qkv_rope_h(
    const __half* __restrict__ A, const __half* __restrict__ W,
    const float* __restrict__ cosp, const float* __restrict__ sinp,
    __half* __restrict__ qo, __half* __restrict__ ko, __half* __restrict__ vo) {
    GEMM_MAINLOOP(A, W)

    const int n0   = bn + wn;          // head-aligned 64-wide warp span
    const int type = n0 >> 9;          // 0=q, 1=k, 2=v
    const int h    = (n0 >> 6) & 7;
    __half* outp = (type == 0) ? qo : (type == 1) ? ko : vo;
    const float sc = (type == 0) ? 0.125f : 1.f;

#pragma unroll
    for (int mi = 0; mi < 2; mi++) {
        const int m  = bm + wm + mi * 16 + g;
        const int b  = m >> 11;
        const int t0 = m & (TT - 1);
        const size_t base0 = ((size_t)(b * HH + h) * TT + t0) * HD;
        const size_t base1 = base0 + 8 * HD;

        if (type == 2) {
#pragma unroll
            for (int ni = 0; ni < 8; ni++) {
                const int d = ni * 8 + 2 * q;
                *(unsigned*)&outp[base0 + d] = pack_h2(acc[mi][ni][0], acc[mi][ni][1]);
                *(unsigned*)&outp[base1 + d] = pack_h2(acc[mi][ni][2], acc[mi][ni][3]);
            }
        } else {
#pragma unroll
            for (int ni = 0; ni < 4; ni++) {
                const int d  = ni * 8 + 2 * q;
                const int du = d + 32;
                float2 cl0 = *(const float2*)&cosp[t0 * HD + d];
                float2 sl0 = *(const float2*)&sinp[t0 * HD + d];
                float2 cu0 = *(const float2*)&cosp[t0 * HD + du];
                float2 su0 = *(const float2*)&sinp[t0 * HD + du];
                float2 cl1 = *(const float2*)&cosp[(t0 + 8) * HD + d];
                float2 sl1 = *(const float2*)&sinp[(t0 + 8) * HD + d];
                float2 cu1 = *(const float2*)&cosp[(t0 + 8) * HD + du];
                float2 su1 = *(const float2*)&sinp[(t0 + 8) * HD + du];

                float x1a = acc[mi][ni][0],     x1b = acc[mi][ni][1];
                float x2a = acc[mi][ni + 4][0], x2b = acc[mi][ni + 4][1];
                *(unsigned*)&outp[base0 + d]  = pack_h2((x1a * cl0.x - x2a * sl0.x) * sc,
                                                        (x1b * cl0.y - x2b * sl0.y) * sc);
                *(unsigned*)&outp[base0 + du] = pack_h2((x2a * cu0.x + x1a * su0.x) * sc,
                                                        (x2b * cu0.y + x1b * su0.y) * sc);
                float y1a = acc[mi][ni][2],     y1b = acc[mi][ni][3];
                float y2a = acc[mi][ni + 4][2], y2b = acc[mi][ni + 4][3];
                *(unsigned*)&outp[base1 + d]  = pack_h2((y1a * cl1.x - y2a * sl1.x) * sc,
                                                        (y1b * cl1.y - y2b * sl1.y) * sc);
                *(unsigned*)&outp[base1 + du] = pack_h2((y2a * cu1.x + y1a * su1.x) * sc,
                                                        (y2b * cu1.y + y1b * su1.y) * sc);
            }
        }
    }
}

// ---- Output projection GEMM (fp16 in, fp32 out) ----
__global__ void __launch_bounds__(256, 2) gemm_out_h(
    const __half* __restrict__ A, const __half* __restrict__ W,
    float* __restrict__ Cmat) {
    GEMM_MAINLOOP(A, W)

#pragma unroll
    for (int mi = 0; mi < 2; mi++) {
#pragma unroll
        for (int ni = 0; ni < 8; ni++) {
            const int m = bm + wm + mi * 16 + g;
            const int n = bn + wn + ni * 8 + 2 * q;
            *(float2*)&Cmat[(size_t)m * CC + n] =
                make_float2(acc[mi][ni][0], acc[mi][ni][1]);
            *(float2*)&Cmat[(size_t)(m + 8) * CC + n] =
                make_float2(acc[mi][ni][2], acc[mi][ni][3]);
        }
    }
}

// =====================================================================
// Flash attention (causal), fp16 in/out, mma m16n8k16 (R14 version:
// wait1-before-compute, two syncs per ktile, unconditional rescale).
// =====================================================================
__global__ void __launch_bounds__(256) attn_h(const __half* __restrict__ Q,
                                              const __half* __restrict__ K,
                                              const __half* __restrict__ V,
                                              __half* __restrict__ Oatt) {
    __shared__ __align__(16) char sma[32768];   // [stage][K 8KB | V 8KB]
    const uint32_t smb = (uint32_t)__cvta_generic_to_shared(sma);

    const int tid  = threadIdx.x;
    const int warp = tid >> 5;
    const int lane = tid & 31;
    const int g    = lane >> 2;
    const int q    = lane & 3;
    const int lg   = lane >> 3, lr = lane & 7;
    const int qt   = (int)gridDim.x - 1 - (int)blockIdx.x;   // big tiles first
    const int q0   = qt * 128;
    const int bh   = blockIdx.y;
    const int row0 = q0 + warp * 16 + g;
    const int row1 = row0 + 8;
    const float L2E = 1.4426950408889634f;

    uint32_t kAdr[4];
#pragma unroll
    for (int kc = 0; kc < 4; kc++)
        kAdr[kc] = (uint32_t)((8 * (lg >> 1) + lr) * 128 +
                              (((2 * kc + (lg & 1)) ^ lr) << 4));
    uint32_t vAdr[4];
#pragma unroll
    for (int jp = 0; jp < 4; jp++)
        vAdr[jp] = (uint32_t)(8192 + (8 * (lg & 1) + lr) * 128 +
                              (((2 * jp + (lg >> 1)) ^ lr) << 4));

    unsigned Qa[4][4];
    {
        const __half* q0p = Q + ((size_t)bh * TT + row0) * HD;
        const __half* q1p = Q + ((size_t)bh * TT + row1) * HD;
#pragma unroll
        for (int kc = 0; kc < 4; kc++) {
            int d0 = 16 * kc + 2 * q;
            Qa[kc][0] = *(const unsigned*)(q0p + d0);
            Qa[kc][1] = *(const unsigned*)(q1p + d0);
            Qa[kc][2] = *(const unsigned*)(q0p + d0 + 8);
            Qa[kc][3] = *(const unsigned*)(q1p + d0 + 8);
        }
    }

    float Oac[8][4];
#pragma unroll
    for (int j = 0; j < 8; j++)
#pragma unroll
        for (int i = 0; i < 4; i++) Oac[j][i] = 0.f;
    float m0_ = -1e30f, m1_ = -1e30f, l0_ = 0.f, l1_ = 0.f;

    const __half* kbase = K + (size_t)bh * TT * HD;
    const __half* vbase = V + (size_t)bh * TT * HD;

    auto load_tile = [&](int s, int k0) {
#pragma unroll
        for (int i = 0; i < 2; i++) {
            int idx = tid + i * 256;              // 0..511 16B chunks
            int key = idx >> 3, c = idx & 7;
            uint32_t doff = (uint32_t)(key * 128 + (((c ^ (key & 7))) << 4));
            const __half* ks = kbase + (size_t)(k0 + key) * HD + 8 * c;
            const __half* vs = vbase + (size_t)(k0 + key) * HD + 8 * c;
            CP_ASYNC16(smb + s * 16384 + doff, ks);
            CP_ASYNC16(smb + s * 16384 + 8192 + doff, vs);
        }
    };

    const int nkt = 2 * qt + 2;
    load_tile(0, 0);
    CP_COMMIT();
    int buf = 0;
    for (int kt = 0; kt < nkt; kt++) {
        const int k0 = kt * 64;
        if (kt + 1 < nkt) load_tile(buf ^ 1, k0 + 64);
        CP_COMMIT();
        CP_WAIT1();
        __syncthreads();
        const uint32_t so = smb + buf * 16384;

        // ---- S = (Q/8) @ K^T ----
        float S[8][4];
#pragma unroll
        for (int j = 0; j < 8; j++)
#pragma unroll
            for (int i = 0; i < 4; i++) S[j][i] = 0.f;

#pragma unroll
        for (int kc = 0; kc < 4; kc++) {
#pragma unroll
            for (int jp = 0; jp < 4; jp++) {
                unsigned b0, b1, b2, b3;
                ldsm_x4(b0, b1, b2, b3, so + kAdr[kc] + jp * 2048);
                mma_f16(S[2 * jp][0], S[2 * jp][1], S[2 * jp][2], S[2 * jp][3],
                        Qa[kc][0], Qa[kc][1], Qa[kc][2], Qa[kc][3], b0, b1);
                mma_f16(S[2 * jp + 1][0], S[2 * jp + 1][1], S[2 * jp + 1][2], S[2 * jp + 1][3],
                        Qa[kc][0], Qa[kc][1], Qa[kc][2], Qa[kc][3], b2, b3);
            }
        }

        // ---- causal mask (last two ktiles straddle the diagonal) ----
        if (kt >= nkt - 2) {
#pragma unroll
            for (int j = 0; j < 8; j++) {
                int c = k0 + 8 * j + 2 * q;
                if (c     > row0) S[j][0] = -1e30f;
                if (c + 1 > row0) S[j][1] = -1e30f;
                if (c     > row1) S[j][2] = -1e30f;
                if (c + 1 > row1) S[j][3] = -1e30f;
            }
        }

        // ---- online softmax (exp via ex2.approx.f16x2) ----
        float tm0 = -1e30f, tm1 = -1e30f;
#pragma unroll
        for (int j = 0; j < 8; j++) {
            tm0 = fmaxf(tm0, fmaxf(S[j][0], S[j][1]));
            tm1 = fmaxf(tm1, fmaxf(S[j][2], S[j][3]));
        }
        tm0 = fmaxf(tm0, __shfl_xor_sync(0xffffffffu, tm0, 1));
        tm0 = fmaxf(tm0, __shfl_xor_sync(0xffffffffu, tm0, 2));
        tm1 = fmaxf(tm1, __shfl_xor_sync(0xffffffffu, tm1, 1));
        tm1 = fmaxf(tm1, __shfl_xor_sync(0xffffffffu, tm1, 2));

        float nm0 = fmaxf(m0_, tm0), nm1 = fmaxf(m1_, tm1);
        float r0 = __expf(m0_ - nm0), r1 = __expf(m1_ - nm1);
        m0_ = nm0; m1_ = nm1;
        const float b0s = nm0 * L2E, b1s = nm1 * L2E;

        unsigned E[8][2];   // E[j][0] = fp16 {p(c0), p(c1)}, E[j][1] = {p(c2), p(c3)}
#pragma unroll
        for (int j = 0; j < 8; j++) {
            float f0 = fmaf(S[j][0], L2E, -b0s);
            float f1 = fmaf(S[j][1], L2E, -b0s);
            float f2 = fmaf(S[j][2], L2E, -b1s);
            float f3 = fmaf(S[j][3], L2E, -b1s);
            E[j][0] = ex2_h2(pack_h2(f0, f1));
            E[j][1] = ex2_h2(pack_h2(f2, f3));
        }

        // row sums via HADD2 tree (sums the exact fp16 P used in PV)
        {
            __half2* Eh = (__half2*)E;
            __half2 s0 = __hadd2(__hadd2(__hadd2(Eh[0],  Eh[2]),  __hadd2(Eh[4],  Eh[6])),
                                 __hadd2(__hadd2(Eh[8],  Eh[10]), __hadd2(Eh[12], Eh[14])));
            __half2 s1 = __hadd2(__hadd2(__hadd2(Eh[1],  Eh[3]),  __hadd2(Eh[5],  Eh[7])),
                                 __hadd2(__hadd2(Eh[9],  Eh[11]), __hadd2(Eh[13], Eh[15])));
            float2 f0 = __half22float2(s0);
            float2 f1 = __half22float2(s1);
            float rs0 = f0.x + f0.y;
            float rs1 = f1.x + f1.y;
            rs0 += __shfl_xor_sync(0xffffffffu, rs0, 1);
            rs0 += __shfl_xor_sync(0xffffffffu, rs0, 2);
            rs1 += __shfl_xor_sync(0xffffffffu, rs1, 1);
            rs1 += __shfl_xor_sync(0xffffffffu, rs1, 2);
            l0_ = l0_ * r0 + rs0;
            l1_ = l1_ * r1 + rs1;
        }

#pragma unroll
        for (int j = 0; j < 8; j++) {
            Oac[j][0] *= r0; Oac[j][1] *= r0;
            Oac[j][2] *= r1; Oac[j][3] *= r1;
        }

        // ---- O += P @ V (P A-frag = E directly; V via ldmatrix.trans) ----
#pragma unroll
        for (int kc = 0; kc < 4; kc++) {
            unsigned a0 = E[2 * kc][0];
            unsigned a1 = E[2 * kc][1];
            unsigned a2 = E[2 * kc + 1][0];
            unsigned a3 = E[2 * kc + 1][1];
#pragma unroll
            for (int jp = 0; jp < 4; jp++) {
                unsigned b0, b1, b2, b3;
                ldsm_x4_t(b0, b1, b2, b3, so + vAdr[jp] + kc * 2048);
                mma_f16(Oac[2 * jp][0], Oac[2 * jp][1], Oac[2 * jp][2], Oac[2 * jp][3],
                        a0, a1, a2, a3, b0, b1);
                mma_f16(Oac[2 * jp + 1][0], Oac[2 * jp + 1][1], Oac[2 * jp + 1][2], Oac[2 * jp + 1][3],
                        a0, a1, a2, a3, b2, b3);
            }
        }
        __syncthreads();   // all warps done reading buf before it is reloaded
        buf ^= 1;
    }

    const int b = bh >> 3, h = bh & 7;
    float inv0 = 1.f / l0_, inv1 = 1.f / l1_;
    __half* o0 = Oatt + ((size_t)(b * TT) + row0) * CC + h * HD;
    __half* o1 = Oatt + ((size_t)(b * TT) + row1) * CC + h * HD;
#pragma unroll
    for (int j = 0; j < 8; j++) {
        *(unsigned*)&o0[8 * j + 2 * q] = pack_h2(Oac[j][0] * inv0, Oac[j][1] * inv0);
        *(unsigned*)&o1[8 * j + 2 * q] = pack_h2(Oac[j][2] * inv1, Oac[j][3] * inv1);
    }
}

// =====================================================================
extern "C" void kernel_launch(void* const* d_in, const int* in_sizes, int n_in,
                              void* d_out, int out_size) {
    const float* x    = (const float*)d_in[0];
    const float* cosp = (const float*)d_in[1];
    const float* sinp = (const float*)d_in[2];
    const float* Wqkv = (const float*)d_in[3];
    const float* Wout = (const float*)d_in[4];
    float* out = (float*)d_out;

    __half *xh, *wqkvh, *wouth, *qh, *kh, *vh, *atth;
    cudaGetSymbolAddress((void**)&xh,    g_xh);
    cudaGetSymbolAddress((void**)&wqkvh, g_wqkvh);
    cudaGetSymbolAddress((void**)&wouth, g_wouth);
    cudaGetSymbolAddress((void**)&qh,    g_qh);
    cudaGetSymbolAddress((void**)&kh,    g_kh);
    cudaGetSymbolAddress((void**)&vh,    g_vh);
    cudaGetSymbolAddress((void**)&atth,  g_atth);

    // opt-in to 64KB dynamic smem for the GEMMs (idempotent, capture-safe)
    const int SMEM = 65536;
    cudaFuncSetAttribute(gemm_qkv_rope_h, cudaFuncAttributeMaxDynamicSharedMemorySize, SMEM);
    cudaFuncSetAttribute(gemm_out_h,      cudaFuncAttributeMaxDynamicSharedMemorySize, SMEM);

    const int na = MM * CC, nb = 3 * CC * CC, nc = CC * CC;
    // 0) fp32 -> fp16 conversion (one launch)
    f2h3<<<(na + nb + nc) / 4 / 256, 256>>>(x, xh, na, Wqkv, wqkvh, nb, Wout, wouth, nc);
    // 1) fused QKV GEMM + RoPE + head-split (fp16 out, q pre-scaled)
    gemm_qkv_rope_h<<<dim3((3 * CC) / 128, MM / 128), 256, SMEM>>>(
        xh, wqkvh, cosp, sinp, qh, kh, vh);
    // 2) causal flash attention (R14 pipeline, f16x2 softmax)
    attn_h<<<dim3(TT / 128, BH), 256>>>(qh, kh, vh, atth);
    // 3) out = att @ Wout^T (fp16 in, fp32 out)
    gemm_out_h<<<dim3(CC / 128, MM / 128), 256, SMEM>>>(atth, wouth, out);
}